// round 1
// baseline (speedup 1.0000x reference)
#include <cuda_runtime.h>
#include <math.h>

// ---------------- model constants ----------------
#define TT   2048      // total tokens B*S
#define DD   2048      // hidden
#define HH   16        // heads
#define HDIM 128       // head dim
#define SS   1024      // seq len
#define BBATCH 2
#define FFN  8192
#define QKN  2304      // D + 2*HD
#define NLAYER 2
#define LN_EPS 1e-5f
#define ATT_SCALE 0.08838834764831845f  // HD^-0.5

// ---------------- scratch (device globals, no allocs) ----------------
__device__ float g_h   [TT * DD];
__device__ float g_res [TT * DD];
__device__ float g_res2[TT * DD];
__device__ float g_x   [TT * DD];
__device__ float g_qkv [TT * QKN];
__device__ float g_ctx [TT * DD];
__device__ float g_attn[TT * DD];
__device__ float g_ff  [TT * FFN];

// ---------------- embed: h = wte[ids] + wpe[pos] ----------------
__global__ void embed_kernel(const int* __restrict__ ids,
                             const int* __restrict__ pos,
                             const float* __restrict__ wte,
                             const float* __restrict__ wpe,
                             float* __restrict__ out)
{
    int idx = blockIdx.x * blockDim.x + threadIdx.x;
    if (idx >= TT * DD) return;
    int t = idx >> 11;       // /DD
    int d = idx & (DD - 1);
    out[idx] = wte[(size_t)ids[t] * DD + d] + wpe[(size_t)pos[t] * DD + d];
}

// ---------------- fused residual-add + LayerNorm ----------------
// res = a + (r ? r : 0); res_out = res (optional); x_out = LN(res)*g + b
__global__ __launch_bounds__(256)
void ln_kernel(const float* __restrict__ a, const float* __restrict__ r,
               const float* __restrict__ g, const float* __restrict__ b,
               float* __restrict__ res_out, float* __restrict__ x_out)
{
    const int t = blockIdx.x;
    const size_t base = (size_t)t * DD;
    float v[8];
    float s = 0.f, sq = 0.f;
#pragma unroll
    for (int i = 0; i < 8; i++) {
        int idx = threadIdx.x + i * 256;
        float val = a[base + idx];
        if (r) val += r[base + idx];
        v[i] = val; s += val; sq += val * val;
    }
    int lane = threadIdx.x & 31, wid = threadIdx.x >> 5;
#pragma unroll
    for (int o = 16; o; o >>= 1) {
        s  += __shfl_xor_sync(0xffffffffu, s,  o);
        sq += __shfl_xor_sync(0xffffffffu, sq, o);
    }
    __shared__ float shs[8], shq[8];
    __shared__ float smean, srstd;
    if (lane == 0) { shs[wid] = s; shq[wid] = sq; }
    __syncthreads();
    if (threadIdx.x == 0) {
        float ts = 0.f, tq = 0.f;
#pragma unroll
        for (int i = 0; i < 8; i++) { ts += shs[i]; tq += shq[i]; }
        float mean = ts * (1.f / DD);
        float var  = tq * (1.f / DD) - mean * mean;
        smean = mean;
        srstd = rsqrtf(var + LN_EPS);
    }
    __syncthreads();
    float mean = smean, rstd = srstd;
#pragma unroll
    for (int i = 0; i < 8; i++) {
        int idx = threadIdx.x + i * 256;
        if (res_out) res_out[base + idx] = v[i];
        x_out[base + idx] = (v[i] - mean) * rstd * g[idx] + b[idx];
    }
}

// ---------------- SGEMM: C[M,N] = A[M,K] @ B[K,N] + bias (+gelu) ----------------
// M,N multiple of 128; K multiple of 8. 128x128 tile, 8x8/thread, double-buffered.
__device__ __forceinline__ float gelu_tanh(float x) {
    float x3 = x * x * x;
    float t = tanhf(0.7978845608028654f * (x + 0.044715f * x3));
    return 0.5f * x * (1.f + t);
}

__global__ __launch_bounds__(256)
void sgemm_kernel(const float* __restrict__ A, const float* __restrict__ B,
                  const float* __restrict__ bias, float* __restrict__ C,
                  int M, int N, int K, int act)
{
    __shared__ float As[2][8][128];
    __shared__ float Bs[2][8][128];

    const int tid = threadIdx.x;
    const int bm = blockIdx.y * 128;
    const int bn = blockIdx.x * 128;

    const int arow = tid >> 1;          // 0..127
    const int acol = (tid & 1) << 2;    // 0 or 4
    const int brow = tid >> 5;          // 0..7
    const int bcol = (tid & 31) << 2;   // 0..124

    const int ty = (tid >> 4) << 3;     // row tile 0..120
    const int tx = (tid & 15) << 3;     // col tile 0..120

    const float* Ag = A + (size_t)(bm + arow) * K + acol;
    const float* Bg = B + (size_t)brow * N + bn + bcol;

    // prologue: tile 0
    {
        float4 av = *(const float4*)Ag;
        float4 bv = *(const float4*)Bg;
        As[0][acol + 0][arow] = av.x;
        As[0][acol + 1][arow] = av.y;
        As[0][acol + 2][arow] = av.z;
        As[0][acol + 3][arow] = av.w;
        *(float4*)&Bs[0][brow][bcol] = bv;
    }
    __syncthreads();

    float acc[8][8] = {};
    int buf = 0;
    const int nk = K >> 3;

#define MMA_TILE(BUF)                                                        \
    {                                                                        \
        _Pragma("unroll")                                                    \
        for (int kk = 0; kk < 8; kk++) {                                     \
            float ar[8], br[8];                                              \
            _Pragma("unroll")                                                \
            for (int i = 0; i < 8; i++) ar[i] = As[BUF][kk][ty + i];         \
            _Pragma("unroll")                                                \
            for (int j = 0; j < 8; j++) br[j] = Bs[BUF][kk][tx + j];         \
            _Pragma("unroll")                                                \
            for (int i = 0; i < 8; i++)                                      \
                _Pragma("unroll")                                            \
                for (int j = 0; j < 8; j++)                                  \
                    acc[i][j] += ar[i] * br[j];                              \
        }                                                                    \
    }

    for (int it = 1; it < nk; it++) {
        const int k0 = it << 3;
        float4 av = *(const float4*)(Ag + k0);
        float4 bv = *(const float4*)(Bg + (size_t)k0 * N);
        MMA_TILE(buf);
        buf ^= 1;
        As[buf][acol + 0][arow] = av.x;
        As[buf][acol + 1][arow] = av.y;
        As[buf][acol + 2][arow] = av.z;
        As[buf][acol + 3][arow] = av.w;
        *(float4*)&Bs[buf][brow][bcol] = bv;
        __syncthreads();
    }
    MMA_TILE(buf);
#undef MMA_TILE

    // epilogue: bias (+gelu), vectorized stores
#pragma unroll
    for (int i = 0; i < 8; i++) {
        const size_t row = (size_t)(bm + ty + i) * N;
#pragma unroll
        for (int j = 0; j < 8; j += 4) {
            int col = bn + tx + j;
            float4 v;
            v.x = acc[i][j + 0] + bias[col + 0];
            v.y = acc[i][j + 1] + bias[col + 1];
            v.z = acc[i][j + 2] + bias[col + 2];
            v.w = acc[i][j + 3] + bias[col + 3];
            if (act) {
                v.x = gelu_tanh(v.x); v.y = gelu_tanh(v.y);
                v.z = gelu_tanh(v.z); v.w = gelu_tanh(v.w);
            }
            *(float4*)(C + row + col) = v;
        }
    }
}

// ---------------- MQA causal attention (online softmax, one warp per q-row/head) ----------------
__global__ __launch_bounds__(256)
void attn_kernel(const float* __restrict__ qkv, float* __restrict__ ctx)
{
    const int gwarp = (blockIdx.x * blockDim.x + threadIdx.x) >> 5;
    const int lane  = threadIdx.x & 31;
    if (gwarp >= BBATCH * HH * SS) return;

    const int s = gwarp & (SS - 1);
    const int h = (gwarp >> 10) & (HH - 1);
    const int b = gwarp >> 14;
    const int t = b * SS + s;

    const float4 q = *(const float4*)(qkv + (size_t)t * QKN + h * HDIM + lane * 4);
    const float* kb = qkv + (size_t)(b * SS) * QKN + DD;        // k at col D
    // v at col D + HDIM = kb + HDIM

    float m = -1e30f, l = 0.f;
    float4 acc = make_float4(0.f, 0.f, 0.f, 0.f);

    for (int j = 0; j <= s; j++) {
        const float* kp = kb + (size_t)j * QKN;
        float4 kv = *(const float4*)(kp + lane * 4);
        float p = q.x * kv.x + q.y * kv.y + q.z * kv.z + q.w * kv.w;
#pragma unroll
        for (int o = 16; o; o >>= 1) p += __shfl_xor_sync(0xffffffffu, p, o);
        p *= ATT_SCALE;
        float nm = fmaxf(m, p);
        float f  = __expf(m - nm);
        float e  = __expf(p - nm);
        m = nm;
        l = l * f + e;
        float4 vv = *(const float4*)(kp + HDIM + lane * 4);
        acc.x = acc.x * f + e * vv.x;
        acc.y = acc.y * f + e * vv.y;
        acc.z = acc.z * f + e * vv.z;
        acc.w = acc.w * f + e * vv.w;
    }
    float inv = 1.f / l;
    float4 o4 = make_float4(acc.x * inv, acc.y * inv, acc.z * inv, acc.w * inv);
    *(float4*)(ctx + (size_t)t * DD + h * HDIM + lane * 4) = o4;
}

// ---------------- launch ----------------
extern "C" void kernel_launch(void* const* d_in, const int* in_sizes, int n_in,
                              void* d_out, int out_size)
{
    const int*   ids      = (const int*)  d_in[0];
    const int*   pos      = (const int*)  d_in[1];
    const float* wte      = (const float*)d_in[2];
    const float* wpe      = (const float*)d_in[3];
    const float* c_attn_w = (const float*)d_in[4];
    const float* c_attn_b = (const float*)d_in[5];
    const float* c_proj_w = (const float*)d_in[6];
    const float* c_proj_b = (const float*)d_in[7];
    const float* ln1_w    = (const float*)d_in[8];
    const float* ln1_b    = (const float*)d_in[9];
    const float* ln2_w    = (const float*)d_in[10];
    const float* ln2_b    = (const float*)d_in[11];
    const float* fc_w     = (const float*)d_in[12];
    const float* fc_b     = (const float*)d_in[13];
    const float* mp_w     = (const float*)d_in[14];
    const float* mp_b     = (const float*)d_in[15];
    const float* lnf_w    = (const float*)d_in[16];
    const float* lnf_b    = (const float*)d_in[17];
    float* out = (float*)d_out;

    float *h, *res, *res2, *x, *qkv, *ctx, *attn, *ff;
    cudaGetSymbolAddress((void**)&h,    g_h);
    cudaGetSymbolAddress((void**)&res,  g_res);
    cudaGetSymbolAddress((void**)&res2, g_res2);
    cudaGetSymbolAddress((void**)&x,    g_x);
    cudaGetSymbolAddress((void**)&qkv,  g_qkv);
    cudaGetSymbolAddress((void**)&ctx,  g_ctx);
    cudaGetSymbolAddress((void**)&attn, g_attn);
    cudaGetSymbolAddress((void**)&ff,   g_ff);

    // embed
    embed_kernel<<<(TT * DD + 255) / 256, 256>>>(ids, pos, wte, wpe, h);

    const dim3 blk(256);
    for (int l = 0; l < NLAYER; l++) {
        const float* law = c_attn_w + (size_t)l * DD * QKN;
        const float* lab = c_attn_b + (size_t)l * QKN;
        const float* lpw = c_proj_w + (size_t)l * DD * DD;
        const float* lpb = c_proj_b + (size_t)l * DD;
        const float* lfw = fc_w     + (size_t)l * DD * FFN;
        const float* lfb = fc_b     + (size_t)l * FFN;
        const float* lmw = mp_w     + (size_t)l * FFN * DD;
        const float* lmb = mp_b     + (size_t)l * DD;

        // ln1: res = h (+ residual), x = LN(res)
        ln_kernel<<<TT, blk>>>(h, (l == 0) ? nullptr : res2,
                               ln1_w + (size_t)l * DD, ln1_b + (size_t)l * DD,
                               res, x);

        // qkv = x @ c_attn_w + b
        sgemm_kernel<<<dim3(QKN / 128, TT / 128), blk>>>(x, law, lab, qkv, TT, QKN, DD, 0);

        // attention -> ctx
        attn_kernel<<<(BBATCH * HH * SS * 32 + 255) / 256, blk>>>(qkv, ctx);

        // attn = ctx @ c_proj_w + b
        sgemm_kernel<<<dim3(DD / 128, TT / 128), blk>>>(ctx, lpw, lpb, attn, TT, DD, DD, 0);

        // ln2: res2 = attn + res, x = LN(res2)
        ln_kernel<<<TT, blk>>>(attn, res,
                               ln2_w + (size_t)l * DD, ln2_b + (size_t)l * DD,
                               res2, x);

        // ff = gelu(x @ fc_w + b)
        sgemm_kernel<<<dim3(FFN / 128, TT / 128), blk>>>(x, lfw, lfb, ff, TT, FFN, DD, 1);

        // h = ff @ mp_w + b
        sgemm_kernel<<<dim3(DD / 128, TT / 128), blk>>>(ff, lmw, lmb, h, TT, DD, FFN, 0);
    }

    // final: out = LN(h + res2)
    ln_kernel<<<TT, blk>>>(h, res2, lnf_w, lnf_b, nullptr, out);
}